// round 3
// baseline (speedup 1.0000x reference)
#include <cuda_runtime.h>
#include <cuda_bf16.h>

#define N_SEL   8192
#define N_FEAT  256
#define K_SUB   256
#define N_PERS  4
#define E_FULL  262144
#define E_RAW   262144
#define N_TOTAL 8192
#define EPSILON 0.5f
#define LAMB1   0.5f

#define N_BLOCKS    1184          // 8 * 148
#define N_FILLB     148           // every 8th block fills
#define N_COMPB     (N_BLOCKS - N_FILLB)   // 1036
#define W_COMPUTE   (N_COMPB * 8) // 8288 compute warps
#define OUT_F4      16777216      // 8192*8192/4

// ---------------- device scratch (no allocations allowed) ----------------
__device__ float        g_rinv[N_SEL * N_PERS];   // interleaved: node-major, 4 floats/node
__device__ float        g_nodew[N_SEL];           // score[batch[i]] * LAMB1
__device__ unsigned int g_bitmap[(size_t)N_SEL * N_SEL / 32];  // 8 MB edge-dedup bitmap
__device__ int          g_nhits;
__device__ int          g_hit_off[E_FULL];
__device__ float        g_hit_val[E_FULL];

// ---------------- score normalization + per-node weight + reset ----------------
__global__ void prep_score_kernel(const float* __restrict__ sc,
                                  const int* __restrict__ belong,
                                  const int* __restrict__ batch) {
    __shared__ float s_sum[K_SUB];
    __shared__ float s_norm[K_SUB];
    int t = threadIdx.x;
    float v = sc[t];
    int   b = belong[t];
    s_sum[t] = 0.f;
    __syncthreads();
    atomicAdd(&s_sum[b], v);
    __syncthreads();
    s_norm[t] = v / s_sum[b];
    if (t == 0) g_nhits = 0;
    __syncthreads();
    for (int i = t; i < N_SEL; i += K_SUB)
        g_nodew[i] = s_norm[batch[i]] * LAMB1;
}

// ---------------- per-node inverse weighted norms + bitmap clear ----------------
__global__ void __launch_bounds__(256) prep_rinv_kernel(const float* __restrict__ x,
                                                        const float* __restrict__ mw) {
    int lane = threadIdx.x & 31;
    const float4* mw4 = reinterpret_cast<const float4*>(mw);
    float4 w0[N_PERS], w1[N_PERS];
    #pragma unroll
    for (int p = 0; p < N_PERS; p++) {
        float4 a = __ldg(mw4 + p * 64 + lane);
        float4 b = __ldg(mw4 + p * 64 + 32 + lane);
        w0[p] = make_float4(a.x * a.x, a.y * a.y, a.z * a.z, a.w * a.w);
        w1[p] = make_float4(b.x * b.x, b.y * b.y, b.z * b.z, b.w * b.w);
    }

    int gtid = blockIdx.x * blockDim.x + threadIdx.x;
    int n = gtid >> 5;

    const float4* xr = reinterpret_cast<const float4*>(x + (size_t)n * N_FEAT);
    float4 a0 = __ldg(xr + lane);
    float4 a1 = __ldg(xr + lane + 32);
    float s0 = a0.x * a0.x, s1 = a0.y * a0.y, s2 = a0.z * a0.z, s3 = a0.w * a0.w;
    float s4 = a1.x * a1.x, s5 = a1.y * a1.y, s6 = a1.z * a1.z, s7 = a1.w * a1.w;

    float acc[N_PERS];
    #pragma unroll
    for (int p = 0; p < N_PERS; p++)
        acc[p] = s0 * w0[p].x + s1 * w0[p].y + s2 * w0[p].z + s3 * w0[p].w
               + s4 * w1[p].x + s5 * w1[p].y + s6 * w1[p].z + s7 * w1[p].w;
    #pragma unroll
    for (int p = 0; p < N_PERS; p++)
        #pragma unroll
        for (int o = 16; o > 0; o >>= 1)
            acc[p] += __shfl_xor_sync(0xffffffffu, acc[p], o);

    if (lane == 0) {
        float4 r = make_float4(1.0f / (sqrtf(acc[0]) + 1e-12f),
                               1.0f / (sqrtf(acc[1]) + 1e-12f),
                               1.0f / (sqrtf(acc[2]) + 1e-12f),
                               1.0f / (sqrtf(acc[3]) + 1e-12f));
        reinterpret_cast<float4*>(g_rinv)[n] = r;
    }

    // clear 8 MB dedup bitmap: 524288 uint4 over 262144 threads -> 2 each
    uint4* bm = reinterpret_cast<uint4*>(g_bitmap);
    uint4 z = make_uint4(0u, 0u, 0u, 0u);
    bm[gtid] = z;
    bm[gtid + 262144] = z;
}

// ---------------- per-edge compute (warp-collective) ----------------
__device__ __forceinline__ void edge_compute(
    int i, int j, int lane,
    float4 a0, float4 a1, float4 b0, float4 b1,
    const float4* w0, const float4* w1,
    const int* __restrict__ smap)
{
    float p0 = a0.x * b0.x, p1 = a0.y * b0.y, p2 = a0.z * b0.z, p3 = a0.w * b0.w;
    float p4 = a1.x * b1.x, p5 = a1.y * b1.y, p6 = a1.z * b1.z, p7 = a1.w * b1.w;

    float acc0 = p0 * w0[0].x + p1 * w0[0].y + p2 * w0[0].z + p3 * w0[0].w
               + p4 * w1[0].x + p5 * w1[0].y + p6 * w1[0].z + p7 * w1[0].w;
    float acc1 = p0 * w0[1].x + p1 * w0[1].y + p2 * w0[1].z + p3 * w0[1].w
               + p4 * w1[1].x + p5 * w1[1].y + p6 * w1[1].z + p7 * w1[1].w;
    float acc2 = p0 * w0[2].x + p1 * w0[2].y + p2 * w0[2].z + p3 * w0[2].w
               + p4 * w1[2].x + p5 * w1[2].y + p6 * w1[2].z + p7 * w1[2].w;
    float acc3 = p0 * w0[3].x + p1 * w0[3].y + p2 * w0[3].z + p3 * w0[3].w
               + p4 * w1[3].x + p5 * w1[3].y + p6 * w1[3].z + p7 * w1[3].w;

    // multi-value warp reduction: 6 shuffles to get class(lane&3) totals
    bool o1 = lane & 1;
    float u0 = o1 ? acc0 : acc1;
    float v0 = (o1 ? acc1 : acc0) + __shfl_xor_sync(0xffffffffu, u0, 1);
    float u1 = o1 ? acc2 : acc3;
    float v1 = (o1 ? acc3 : acc2) + __shfl_xor_sync(0xffffffffu, u1, 1);
    bool o2 = lane & 2;
    float t  = o2 ? v0 : v1;
    float w  = (o2 ? v1 : v0) + __shfl_xor_sync(0xffffffffu, t, 2);
    w += __shfl_xor_sync(0xffffffffu, w, 4);
    w += __shfl_xor_sync(0xffffffffu, w, 8);
    w += __shfl_xor_sync(0xffffffffu, w, 16);
    // now every lane l holds total of acc[(l&1) + 2*((l>>1)&1)] ... class = lane&3
    // mapping check: lane0->acc0, lane1->acc1, lane2->acc2, lane3->acc3

    int c = lane & 3;
    float ri = __ldg(g_rinv + 4 * i + c);
    float rj = __ldg(g_rinv + 4 * j + c);
    float s = w * ri * rj;
    s += __shfl_xor_sync(0xffffffffu, s, 1);
    s += __shfl_xor_sync(0xffffffffu, s, 2);

    if (lane == 0) {
        float sim = 0.25f * s;
        if (sim > EPSILON && i != j) {
            size_t idx = (size_t)i * N_SEL + j;
            unsigned bit = 1u << (idx & 31u);
            unsigned old = atomicOr(&g_bitmap[idx >> 5], bit);
            if (!(old & bit)) {
                int slot = atomicAdd(&g_nhits, 1);
                g_hit_off[slot] = __ldg(smap + i) * N_TOTAL + __ldg(smap + j);
                g_hit_val[slot] = sim * g_nodew[i];
            }
        }
    }
}

// ---------------- main kernel: fill blocks + compute blocks in one grid ----------------
__global__ void __launch_bounds__(256) main_kernel(const float* __restrict__ x,
                                                   const float* __restrict__ mw,
                                                   const int* __restrict__ fe,
                                                   const int* __restrict__ smap,
                                                   float4* __restrict__ out4) {
    int bid = blockIdx.x;
    int tid = threadIdx.x;

    if ((bid & 7) == 7) {
        // ---- fill block: streaming zero of 256 MB output ----
        int fb = bid >> 3;                      // 0..147
        float4 z = make_float4(0.f, 0.f, 0.f, 0.f);
        for (int i = fb * 256 + tid; i < OUT_F4; i += N_FILLB * 256)
            __stcs(out4 + i, z);
        return;
    }

    // ---- compute block ----
    int lane = tid & 31;
    const float4* mw4 = reinterpret_cast<const float4*>(mw);
    float4 w0[N_PERS], w1[N_PERS];
    #pragma unroll
    for (int p = 0; p < N_PERS; p++) {
        float4 a = __ldg(mw4 + p * 64 + lane);
        float4 b = __ldg(mw4 + p * 64 + 32 + lane);
        w0[p] = make_float4(a.x * a.x, a.y * a.y, a.z * a.z, a.w * a.w);
        w1[p] = make_float4(b.x * b.x, b.y * b.y, b.z * b.z, b.w * b.w);
    }

    int cbid = bid - (bid >> 3);                // 0..1035 (skip fill blocks)
    int warp = cbid * 8 + (tid >> 5);           // 0..8287

    for (int e = warp; e < E_FULL; e += 2 * W_COMPUTE) {
        int e2 = e + W_COMPUTE;
        bool has2 = e2 < E_FULL;

        int i1 = __ldg(fe + e);
        int j1 = __ldg(fe + E_FULL + e);
        int i2 = has2 ? __ldg(fe + e2) : i1;
        int j2 = has2 ? __ldg(fe + E_FULL + e2) : j1;

        // issue all 8 row loads up front (MLP 8)
        const float4* xi1 = reinterpret_cast<const float4*>(x + (size_t)i1 * N_FEAT);
        const float4* xj1 = reinterpret_cast<const float4*>(x + (size_t)j1 * N_FEAT);
        const float4* xi2 = reinterpret_cast<const float4*>(x + (size_t)i2 * N_FEAT);
        const float4* xj2 = reinterpret_cast<const float4*>(x + (size_t)j2 * N_FEAT);
        float4 a0 = __ldg(xi1 + lane), a1 = __ldg(xi1 + lane + 32);
        float4 b0 = __ldg(xj1 + lane), b1 = __ldg(xj1 + lane + 32);
        float4 c0 = __ldg(xi2 + lane), c1 = __ldg(xi2 + lane + 32);
        float4 d0 = __ldg(xj2 + lane), d1 = __ldg(xj2 + lane + 32);

        edge_compute(i1, j1, lane, a0, a1, b0, b1, w0, w1, smap);
        if (has2)
            edge_compute(i2, j2, lane, c0, c1, d0, d1, w0, w1, smap);
    }
}

// ---------------- scatter: raw edges + thresholded hits ----------------
__global__ void scatter_kernel(const int* __restrict__ re, float* __restrict__ out) {
    int t = blockIdx.x * blockDim.x + threadIdx.x;   // exactly E_RAW threads
    int r = __ldg(re + t);
    int c = __ldg(re + E_RAW + t);
    atomicAdd(out + (size_t)r * N_TOTAL + c, 1.0f - LAMB1);
    if (t < g_nhits)
        atomicAdd(out + g_hit_off[t], g_hit_val[t]);
}

// ---------------- launch ----------------
extern "C" void kernel_launch(void* const* d_in, const int* in_sizes, int n_in,
                              void* d_out, int out_size) {
    const float* x      = (const float*)d_in[0];   // [8192, 256]
    const float* mw     = (const float*)d_in[1];   // [4, 256]
    const int*   batch  = (const int*)  d_in[2];   // [8192]
    const int*   smap   = (const int*)  d_in[3];   // [8192]
    const int*   belong = (const int*)  d_in[4];   // [256]
    const float* score  = (const float*)d_in[5];   // [256]
    const int*   fe     = (const int*)  d_in[6];   // [2, 262144]
    const int*   re     = (const int*)  d_in[7];   // [2, 262144]
    float* out = (float*)d_out;                    // [8192, 8192]

    prep_score_kernel<<<1, 256>>>(score, belong, batch);
    prep_rinv_kernel<<<1024, 256>>>(x, mw);                // rinv + bitmap clear
    main_kernel<<<N_BLOCKS, 256>>>(x, mw, fe, smap,
                                   reinterpret_cast<float4*>(out));
    scatter_kernel<<<E_RAW / 256, 256>>>(re, out);
}